// round 8
// baseline (speedup 1.0000x reference)
#include <cuda_runtime.h>
#include <cstdint>

#define BS 4
#define SQ 1024
#define CH 64
#define UN 32
#define TSPAN 72
#define GRID (BS * 128)

__device__ float g_k[BS * SQ * UN];
__device__ unsigned g_flag[GRID];   // monotonic per-block launch counters

__device__ __forceinline__ float htanh(float x) {
    float y;
    asm("tanh.approx.f32 %0, %1;" : "=f"(y) : "f"(x));
    return y;
}

// shared pool layout (floats)
#define OFF_XTS  0                    // xts [72][68]             = 4896
#define OFF_U1   4896                 // ph1: wts[32][68]+wxs[32][68] (4352)
                                      // ph2: ks[72][36] (2592) + vs[32][68] (2176)
#define OFF_QS   (4896 + 4768)        // qs [8][32]               = 256
#define OFF_AXS  (OFF_QS + 256)       // ph1: xs[8][64] / ph2: a_s[8][64] = 512
#define OFF_WAS  (OFF_AXS + 512)      // 32
#define OFF_SUM  (OFF_WAS + 32)       // 16
#define SMEM_FLOATS (OFF_SUM + 16)    // 10480 floats = 41.9KB

// ---------------------------------------------------------------------------
// Fused kernel, neighbor-only sync, warp-specialized phase 1:
//   warps 0-7: q+k dots for own 8 rows (shared x-row);  k -> g_k, q -> qs
//   warps 8-15: entire xts halo fill (XOR-swizzled), in parallel
// then flag release + <=9 neighbor spin, ks halo fill (float4, [ti][u] s36),
// scores (vector k loads), 1-barrier softmax, a-write, v-pass, v-combine.
// ---------------------------------------------------------------------------
__global__ __launch_bounds__(512, 4) void fused_kernel(
    const float* __restrict__ x,
    const float* __restrict__ Wt,
    const float* __restrict__ Wx,
    const float* __restrict__ bh,
    const float* __restrict__ wa,
    float* __restrict__ vout,
    float* __restrict__ aout)
{
    __shared__ __align__(16) float pool[SMEM_FLOATS];
    __shared__ unsigned smyval;

    float* xts = pool + OFF_XTS;   // [ti][c-swizzled], stride 68
    float* qs  = pool + OFF_QS;    // [r][u]
    float* was = pool + OFF_WAS;
    float* sumb = pool + OFF_SUM;  // [r*2+h]

    int b = blockIdx.x >> 7;
    int sblk = blockIdx.x & 127;
    int s0 = sblk << 3;
    int tid = threadIdx.x;
    int wid = tid >> 5, ln = tid & 31;
    int tlo = s0 - 32;

    // ================= cooperative loads =================
    {
        float* wts = pool + OFF_U1;          // [u][c], stride 68 (17 units, odd)
        float* wxs = wts + UN * 68;
        float* xs  = pool + OFF_AXS;         // [s][c], stride 64
        int u = tid >> 4, g = tid & 15;      // 512 = 32u x 16 groups
        *(float4*)&wts[u * 68 + g * 4] = ((const float4*)Wt)[tid];
        *(float4*)&wxs[u * 68 + g * 4] = ((const float4*)Wx)[tid];
        int c = tid >> 3, s = tid & 7;       // 512 = 64c x 8s
        xs[s * 64 + c] = x[(size_t)b * CH * SQ + c * SQ + s0 + s];
        if (tid < UN) was[tid] = wa[tid];
    }
    __syncthreads();                         // SYNC_A

    // ================= phase 1 (specialized) =================
    if (wid < 8) {
        // q and k for row s = wid, unit u = ln (shared x-row read)
        const float* wts = pool + OFF_U1;
        const float* wxs = wts + UN * 68;
        const float* xs  = pool + OFF_AXS;
        const float4* xp  = (const float4*)&xs[wid * 64];
        const float4* wtp = (const float4*)&wts[ln * 68];
        const float4* wxp = (const float4*)&wxs[ln * 68];
        float q0 = 0.f, q1 = 0.f, q2 = 0.f, q3 = 0.f;
        float k0 = 0.f, k1 = 0.f, k2 = 0.f, k3 = 0.f;
#pragma unroll
        for (int it = 0; it < 16; it++) {
            float4 x4 = xp[it];
            float4 wt = wtp[it];
            float4 wx = wxp[it];
            q0 = fmaf(x4.x, wt.x, q0); q1 = fmaf(x4.y, wt.y, q1);
            q2 = fmaf(x4.z, wt.z, q2); q3 = fmaf(x4.w, wt.w, q3);
            k0 = fmaf(x4.x, wx.x, k0); k1 = fmaf(x4.y, wx.y, k1);
            k2 = fmaf(x4.z, wx.z, k2); k3 = fmaf(x4.w, wx.w, k3);
        }
        qs[wid * 32 + ln] = (q0 + q1) + (q2 + q3);
        g_k[((size_t)b * SQ + s0 + wid) * UN + ln] =
            (k0 + k1) + (k2 + k3) + bh[ln];          // bh folded into k
    } else {
        // entire xts halo fill: 256 threads x 18 = 72 rows x 64 c
        int tid2 = tid - 256;
        int cc0 = (tid2 >> 3) << 1;      // channel pair base
        int t8 = tid2 & 7;
        const float* xbase = x + (size_t)b * CH * SQ;
#pragma unroll
        for (int half = 0; half < 2; half++) {
            int cc = cc0 + half;
            int gbase = cc >> 2, clo = cc & 3;
            const float* xb = xbase + cc * SQ;
#pragma unroll
            for (int p = 0; p < 9; p++) {
                int ti = p * 8 + t8;
                int tc = min(max(tlo + ti, 0), SQ - 1);
                int csw = ((gbase ^ t8) << 2) | clo;   // ti&7 == t8
                xts[ti * 68 + csw] = xb[tc];
            }
        }
    }
    __syncthreads();                         // SYNC_B: k stored, xts done

    // release own flag (fence orders k stores), spin on <=9 neighbors
    if (tid == 0) {
        __threadfence();
        smyval = atomicAdd(&g_flag[blockIdx.x], 1u) + 1u;
    }
    if (tid < 32) {
        __syncwarp();
        int nlo = max(sblk - 4, 0);
        int nhi = min(sblk + 4, 127);
        if (tid <= nhi - nlo) {
            unsigned mv = smyval;
            volatile unsigned* f = (volatile unsigned*)&g_flag[(b << 7) + nlo + tid];
            while (*f < mv) { }
            __threadfence();                 // acquire
        }
        __syncwarp();
    }
    __syncthreads();                         // SYNC_C: neighbors' k visible

    // ks halo fill: [ti][u], stride 36 (9 units, odd -> conflict-free LDS.128)
    float* ks = pool + OFF_U1;               // 72*36 = 2592
    {
        const float4* gk4 = (const float4*)g_k;
#pragma unroll
        for (int lin = tid; lin < TSPAN * 8; lin += 512) {
            int ti = lin >> 3, g = lin & 7;
            int tc = min(max(tlo + ti, 0), SQ - 1);
            *(float4*)&ks[ti * 36 + g * 4] = gk4[((size_t)b * SQ + tc) * 8 + g];
        }
    }
    __syncthreads();                         // SYNC_D

    // ================= phase 2: scores + softmax =================
    int r = wid >> 1;           // query row in block
    int h = wid & 1;            // window half
    int s = s0 + r;
    int j = h * 32 + ln;
    int t = s - 32 + j;
    bool valid = (t >= 0) && (t < SQ);
    int ti = r + j;             // <= 70

    const float4* kp = (const float4*)&ks[ti * 36];
    const float4* qp = (const float4*)&qs[r * 32];
    const float4* wap = (const float4*)was;
    float acc = 0.f;
#pragma unroll
    for (int g = 0; g < 8; g++) {
        float4 q4 = qp[g];
        float4 w4 = wap[g];
        float4 k4 = kp[g];
        acc = fmaf(w4.x, htanh(q4.x + k4.x), acc);
        acc = fmaf(w4.y, htanh(q4.y + k4.y), acc);
        acc = fmaf(w4.z, htanh(q4.z + k4.z), acc);
        acc = fmaf(w4.w, htanh(q4.w + k4.w), acc);
    }

    // softmax without max-shift (scores bounded by sum|wa|; shift cancels
    // except through eps: rel err <= ~1.3e-5)
    float* a_s = pool + OFF_AXS;             // reuse xs region
    float e = valid ? __expf(acc) : 0.f;
    float sm = e;
#pragma unroll
    for (int o = 16; o > 0; o >>= 1) sm += __shfl_xor_sync(0xffffffffu, sm, o);
    if (ln == 0) sumb[r * 2 + h] = sm;
    a_s[(r << 6) + j] = e;                   // unnormalized
    __syncthreads();                         // SYNC_E

    float inv = __fdividef(1.f, sumb[r * 2] + sumb[r * 2 + 1] + 1e-7f);

    // --- a row write: warp-uniform branch; window hits <=2 of 8 segments ---
    float4 z4 = make_float4(0.f, 0.f, 0.f, 0.f);
    float4* arow = (float4*)(aout + (((size_t)b * SQ + s) << 10));
#pragma unroll
    for (int i = 0; i < 4; i++) {
        int col0 = (h << 9) + (i << 7);
        int col = col0 + (ln << 2);
        if (col0 > s + 31 || col0 + 127 < s - 32) {
            arow[col >> 2] = z4;
        } else {
            int jw = col - s + 32;
            float4 val;
            val.x = ((unsigned)(jw + 0) < 64u) ? a_s[(r << 6) + jw + 0] * inv : 0.f;
            val.y = ((unsigned)(jw + 1) < 64u) ? a_s[(r << 6) + jw + 1] * inv : 0.f;
            val.z = ((unsigned)(jw + 2) < 64u) ? a_s[(r << 6) + jw + 2] * inv : 0.f;
            val.w = ((unsigned)(jw + 3) < 64u) ? a_s[(r << 6) + jw + 3] * inv : 0.f;
            arow[col >> 2] = val;
        }
    }

    // --- v pass: per row, 64 threads = 16 channel-groups x 4 j-segments ---
    float* vs = pool + OFF_U1 + 2592;        // [32][68]
    {
        int q64 = tid & 63;
        int cgrp = q64 & 15;
        int jseg = q64 >> 4;
        float4 vacc = z4;
#pragma unroll
        for (int it = 0; it < 16; it++) {
            int jj = jseg * 16 + it;
            int row = r + jj;
            float av = a_s[(r << 6) + jj];
            float4 x4 = *(const float4*)&xts[row * 68 + ((cgrp ^ (row & 7)) << 2)];
            vacc.x = fmaf(av, x4.x, vacc.x);
            vacc.y = fmaf(av, x4.y, vacc.y);
            vacc.z = fmaf(av, x4.z, vacc.z);
            vacc.w = fmaf(av, x4.w, vacc.w);
        }
        vacc.x *= inv; vacc.y *= inv; vacc.z *= inv; vacc.w *= inv;
        *(float4*)&vs[((r << 2) + jseg) * 68 + (cgrp << 2)] = vacc;
    }
    __syncthreads();                         // SYNC_F

    // combine 4 j-segment partials + coalesced transposed v write
    {
        int c = tid >> 3, i = tid & 7;
        float vsum = (vs[(i * 4 + 0) * 68 + c] + vs[(i * 4 + 1) * 68 + c]) +
                     (vs[(i * 4 + 2) * 68 + c] + vs[(i * 4 + 3) * 68 + c]);
        vout[(size_t)b * CH * SQ + c * SQ + s0 + i] = vsum;
    }
}

extern "C" void kernel_launch(void* const* d_in, const int* in_sizes, int n_in,
                              void* d_out, int out_size) {
    (void)in_sizes; (void)n_in; (void)out_size;
    const float* x  = (const float*)d_in[0];
    const float* Wt = (const float*)d_in[1];
    const float* Wx = (const float*)d_in[2];
    const float* Wa = (const float*)d_in[3];
    // d_in[4] = Wa_b: cancels exactly in the softmax, unused
    const float* bh = (const float*)d_in[5];

    float* vout = (float*)d_out;                     // (B, C, S)
    float* aout = vout + (size_t)BS * CH * SQ;       // (B, S, S)

    fused_kernel<<<GRID, 512>>>(x, Wt, Wx, bh, Wa, vout, aout);
}

// round 9
// speedup vs baseline: 1.0311x; 1.0311x over previous
#include <cuda_runtime.h>
#include <cstdint>

#define BS 4
#define SQ 1024
#define CH 64
#define UN 32
#define TSPAN 72
#define GRID (BS * 128)

__device__ float g_k[BS * SQ * UN];
__device__ unsigned g_flag[GRID];   // monotonic per-block launch counters

__device__ __forceinline__ float htanh(float x) {
    float y;
    asm("tanh.approx.f32 %0, %1;" : "=f"(y) : "f"(x));
    return y;
}

// shared pool (floats)
#define OFF_XTS  0                    // xts [72][68] = 4896
#define OFF_U1   4896                 // ph1: wts[32][68]+wxs[32][68] = 4352
                                      // ph2: ks[72][36]=2592 + vs[32][68]=2176
#define OFF_QS   (4896 + 4768)        // qs [8][32] = 256
#define OFF_AXS  (OFF_QS + 256)       // ph1: xs[8][64] / ph2: a_s[8][64] = 512
#define OFF_WAS  (OFF_AXS + 512)      // 32
#define OFF_SUM  (OFF_WAS + 32)       // 16
#define SMEM_FLOATS (OFF_SUM + 16)

__global__ __launch_bounds__(512, 4) void fused_kernel(
    const float* __restrict__ x,
    const float* __restrict__ Wt,
    const float* __restrict__ Wx,
    const float* __restrict__ bh,
    const float* __restrict__ wa,
    float* __restrict__ vout,
    float* __restrict__ aout)
{
    __shared__ __align__(16) float pool[SMEM_FLOATS];
    __shared__ unsigned smyval;

    float* xts  = pool + OFF_XTS;   // [ti][c-swizzled], stride 68
    float* qs   = pool + OFF_QS;    // [r][u]
    float* was  = pool + OFF_WAS;
    float* sumb = pool + OFF_SUM;   // [r*2+h]

    int b = blockIdx.x >> 7;
    int sblk = blockIdx.x & 127;
    int s0 = sblk << 3;
    int tid = threadIdx.x;
    int wid = tid >> 5, ln = tid & 31;
    int r = wid >> 1;               // query row in block
    int h = wid & 1;                // window half
    int s = s0 + r;
    int tlo = s0 - 32;

    // ---- hoisted: zero-fill inactive a segments (overlaps load latency) ----
    float4 z4 = make_float4(0.f, 0.f, 0.f, 0.f);
    float4* arow = (float4*)(aout + (((size_t)b * SQ + s) << 10));
#pragma unroll
    for (int i = 0; i < 4; i++) {
        int col0 = (h << 9) + (i << 7);
        if (col0 > s + 31 || col0 + 127 < s - 32)
            arow[(col0 >> 2) + ln] = z4;
    }

    // ================= cooperative loads =================
    {
        float* wts = pool + OFF_U1;          // [u][c], stride 68
        float* wxs = wts + UN * 68;
        float* xs  = pool + OFF_AXS;         // [s][c], stride 64
        int u = tid >> 4, g = tid & 15;      // 512 = 32u x 16 groups
        *(float4*)&wts[u * 68 + g * 4] = ((const float4*)Wt)[tid];
        *(float4*)&wxs[u * 68 + g * 4] = ((const float4*)Wx)[tid];
        int c = tid >> 3, sr = tid & 7;      // 512 = 64c x 8s
        xs[sr * 64 + c] = x[(size_t)b * CH * SQ + c * SQ + s0 + sr];
        if (tid < UN) was[tid] = wa[tid];
    }
    __syncthreads();                         // SYNC_A

    // ================= phase 1: symmetric (r7 style) =================
    {
        const float* wts = pool + OFF_U1;
        const float* wxs = wts + UN * 68;
        const float* xs  = pool + OFF_AXS;
        int ss = (tid >> 5) & 7;             // warps 0-7: q rows; 8-15: k rows
        const float* wrow = (tid < 256) ? &wts[ln * 68] : &wxs[ln * 68];
        const float4* xp = (const float4*)&xs[ss * 64];
        const float4* wp = (const float4*)wrow;
        float a0 = 0.f, a1 = 0.f, a2 = 0.f, a3 = 0.f;
#pragma unroll
        for (int it = 0; it < 16; it++) {
            float4 x4 = xp[it];
            float4 w4 = wp[it];
            a0 = fmaf(x4.x, w4.x, a0); a1 = fmaf(x4.y, w4.y, a1);
            a2 = fmaf(x4.z, w4.z, a2); a3 = fmaf(x4.w, w4.w, a3);
        }
        float res = (a0 + a1) + (a2 + a3);
        if (tid < 256) {
            qs[ss * 32 + ln] = res;
        } else {
            g_k[((size_t)b * SQ + s0 + ss) * UN + ln] = res + bh[ln];  // bh folded
        }
    }
    __syncthreads();                         // SYNC_B: k stored, w/xs free

    // release own flag, spin on <=9 neighbors (warp 0, overlapped with fill)
    if (tid == 0) {
        __threadfence();
        smyval = atomicAdd(&g_flag[blockIdx.x], 1u) + 1u;
    }
    if (tid < 32) {
        __syncwarp();
        int nlo = max(sblk - 4, 0);
        int nhi = min(sblk + 4, 127);
        if (tid <= nhi - nlo) {
            unsigned mv = smyval;
            volatile unsigned* f = (volatile unsigned*)&g_flag[(b << 7) + nlo + tid];
            while (*f < mv) { }
            __threadfence();                 // acquire
        }
        __syncwarp();
    }

    // ---- xts halo fill: vector path for interior blocks ----
    {
        int cc = tid >> 3, g = tid & 7;
        int gb = cc >> 2, clo = cc & 3;
        const float* xb = x + (size_t)b * CH * SQ + cc * SQ;
        if (sblk >= 4 && sblk <= 123) {
            const float4* xb4 = (const float4*)(xb + tlo);   // tlo % 4 == 0
#pragma unroll
            for (int f = 0; f < 3; f++) {
                int fi = g + f * 8;
                if (fi < 18) {
                    float4 v = xb4[fi];
                    int t0 = fi << 2;
                    xts[(t0 + 0) * 68 + (((((t0 + 0) & 7) ^ gb) << 2) | clo)] = v.x;
                    xts[(t0 + 1) * 68 + (((((t0 + 1) & 7) ^ gb) << 2) | clo)] = v.y;
                    xts[(t0 + 2) * 68 + (((((t0 + 2) & 7) ^ gb) << 2) | clo)] = v.z;
                    xts[(t0 + 3) * 68 + (((((t0 + 3) & 7) ^ gb) << 2) | clo)] = v.w;
                }
            }
        } else {
#pragma unroll
            for (int p = 0; p < 9; p++) {
                int ti = p * 8 + g;
                int tc = min(max(tlo + ti, 0), SQ - 1);
                int csw = ((gb ^ g) << 2) | clo;   // ti&7 == g
                xts[ti * 68 + csw] = xb[tc];
            }
        }
    }
    __syncthreads();                         // SYNC_C: xts done, neighbor k visible

    // ---- ks halo fill: [ti][u] stride 36 (odd 16B units), LDG.128/STS.128 ----
    float* ks = pool + OFF_U1;               // 72*36 = 2592
    {
        const float4* gk4 = (const float4*)g_k;
        {
            int ti = tid >> 3, gq = tid & 7;
            int tc = min(max(tlo + ti, 0), SQ - 1);
            *(float4*)&ks[ti * 36 + gq * 4] = gk4[((size_t)b * SQ + tc) * 8 + gq];
        }
        if (tid < 64) {
            int ti = 64 + (tid >> 3), gq = tid & 7;
            int tc = min(max(tlo + ti, 0), SQ - 1);
            *(float4*)&ks[ti * 36 + gq * 4] = gk4[((size_t)b * SQ + tc) * 8 + gq];
        }
    }
    __syncthreads();                         // SYNC_D

    // ================= phase 2: scores + softmax =================
    int j = h * 32 + ln;
    int t = s - 32 + j;
    bool valid = (t >= 0) && (t < SQ);
    int ti = r + j;                          // <= 70

    const float4* kp = (const float4*)&ks[ti * 36];
    const float4* qp = (const float4*)&qs[r * 32];
    const float4* wap = (const float4*)was;
    float acc = 0.f;
#pragma unroll
    for (int g = 0; g < 8; g++) {
        float4 q4 = qp[g];
        float4 w4 = wap[g];
        float4 k4 = kp[g];
        acc = fmaf(w4.x, htanh(q4.x + k4.x), acc);
        acc = fmaf(w4.y, htanh(q4.y + k4.y), acc);
        acc = fmaf(w4.z, htanh(q4.z + k4.z), acc);
        acc = fmaf(w4.w, htanh(q4.w + k4.w), acc);
    }

    // softmax without max-shift (scores bounded by sum|wa|; shift cancels
    // except through eps: rel err <= ~1.3e-5)
    float* a_s = pool + OFF_AXS;             // reuse xs region
    float e = valid ? __expf(acc) : 0.f;
    float sm = e;
#pragma unroll
    for (int o = 16; o > 0; o >>= 1) sm += __shfl_xor_sync(0xffffffffu, sm, o);
    if (ln == 0) sumb[r * 2 + h] = sm;
    a_s[(r << 6) + j] = e;                   // unnormalized
    __syncthreads();                         // SYNC_E

    float inv = __fdividef(1.f, sumb[r * 2] + sumb[r * 2 + 1] + 1e-7f);

    // ---- a row write: ACTIVE segments only (zeros already written) ----
#pragma unroll
    for (int i = 0; i < 4; i++) {
        int col0 = (h << 9) + (i << 7);
        if (!(col0 > s + 31 || col0 + 127 < s - 32)) {
            int col = col0 + (ln << 2);
            int jw = col - s + 32;
            float4 val;
            val.x = ((unsigned)(jw + 0) < 64u) ? a_s[(r << 6) + jw + 0] * inv : 0.f;
            val.y = ((unsigned)(jw + 1) < 64u) ? a_s[(r << 6) + jw + 1] * inv : 0.f;
            val.z = ((unsigned)(jw + 2) < 64u) ? a_s[(r << 6) + jw + 2] * inv : 0.f;
            val.w = ((unsigned)(jw + 3) < 64u) ? a_s[(r << 6) + jw + 3] * inv : 0.f;
            arow[col >> 2] = val;
        }
    }

    // ---- v pass: per row, 64 threads = 16 c-groups x 4 j-segments ----
    float* vs = pool + OFF_U1 + 2592;        // [32][68]
    {
        int q64 = tid & 63;
        int cgrp = q64 & 15;
        int jseg = q64 >> 4;
        float4 vacc = z4;
#pragma unroll
        for (int it2 = 0; it2 < 4; it2++) {
            float4 a4 = *(const float4*)&a_s[(r << 6) + (jseg << 4) + (it2 << 2)];
            int jb = (jseg << 4) + (it2 << 2);
#pragma unroll
            for (int ee = 0; ee < 4; ee++) {
                int row = r + jb + ee;
                float av = (ee == 0) ? a4.x : (ee == 1) ? a4.y : (ee == 2) ? a4.z : a4.w;
                float4 x4 = *(const float4*)&xts[row * 68 + ((cgrp ^ (row & 7)) << 2)];
                vacc.x = fmaf(av, x4.x, vacc.x);
                vacc.y = fmaf(av, x4.y, vacc.y);
                vacc.z = fmaf(av, x4.z, vacc.z);
                vacc.w = fmaf(av, x4.w, vacc.w);
            }
        }
        vacc.x *= inv; vacc.y *= inv; vacc.z *= inv; vacc.w *= inv;
        *(float4*)&vs[((r << 2) + jseg) * 68 + (cgrp << 2)] = vacc;
    }
    __syncthreads();                         // SYNC_F

    // combine 4 j-segment partials + coalesced transposed v write
    {
        int c = tid >> 3, i = tid & 7;
        float vsum = (vs[(i * 4 + 0) * 68 + c] + vs[(i * 4 + 1) * 68 + c]) +
                     (vs[(i * 4 + 2) * 68 + c] + vs[(i * 4 + 3) * 68 + c]);
        vout[(size_t)b * CH * SQ + c * SQ + s0 + i] = vsum;
    }
}

extern "C" void kernel_launch(void* const* d_in, const int* in_sizes, int n_in,
                              void* d_out, int out_size) {
    (void)in_sizes; (void)n_in; (void)out_size;
    const float* x  = (const float*)d_in[0];
    const float* Wt = (const float*)d_in[1];
    const float* Wx = (const float*)d_in[2];
    const float* Wa = (const float*)d_in[3];
    // d_in[4] = Wa_b: cancels exactly in the softmax, unused
    const float* bh = (const float*)d_in[5];

    float* vout = (float*)d_out;                     // (B, C, S)
    float* aout = vout + (size_t)BS * CH * SQ;       // (B, S, S)

    fused_kernel<<<GRID, 512>>>(x, Wt, Wx, bh, Wa, vout, aout);
}

// round 10
// speedup vs baseline: 1.1218x; 1.0880x over previous
#include <cuda_runtime.h>
#include <cstdint>

#define BS 4
#define SQ 1024
#define CH 64
#define UN 32
#define TSPAN 72
#define GRID (BS * 128)

__device__ float g_k[BS * SQ * UN];
__device__ unsigned g_flag[GRID];   // monotonic; +9 per block per launch

__device__ __forceinline__ float htanh(float x) {
    float y;
    asm("tanh.approx.f32 %0, %1;" : "=f"(y) : "f"(x));
    return y;
}

// shared pool (floats)
#define OFF_XTS  0                    // xts [72][68] = 4896
#define OFF_U1   4896                 // ph1: wts[32][68]+wxs[32][68]=4352
                                      // ph2: ks[72][36]=2592 + vs 2208 = 4800
#define OFF_QS   (4896 + 4800)        // qs [8][32] = 256
#define OFF_AS   (OFF_QS + 256)       // a_s [8][64] = 512
#define OFF_WAS  (OFF_AS + 512)       // 32
#define OFF_SUM  (OFF_WAS + 32)       // 16
#define SMEM_FLOATS (OFF_SUM + 16)

__global__ __launch_bounds__(512, 4) void fused_kernel(
    const float* __restrict__ x,
    const float* __restrict__ Wt,
    const float* __restrict__ Wx,
    const float* __restrict__ bh,
    const float* __restrict__ wa,
    float* __restrict__ vout,
    float* __restrict__ aout)
{
    __shared__ __align__(16) float pool[SMEM_FLOATS];

    float* xts  = pool + OFF_XTS;   // [ti][c-swizzled], stride 68
    float* qs   = pool + OFF_QS;    // [r][u]
    float* was  = pool + OFF_WAS;
    float* sumb = pool + OFF_SUM;   // [r*2+h]

    int b = blockIdx.x >> 7;
    int sblk = blockIdx.x & 127;
    int s0 = sblk << 3;
    int tid = threadIdx.x;
    int wid = tid >> 5, ln = tid & 31;
    int r = wid >> 1;               // query row in block
    int h = wid & 1;                // window half
    int s = s0 + r;
    int tlo = s0 - 32;

    // ---- top: zero-fill inactive a segments (fire-and-forget STG) ----
    float4 z4 = make_float4(0.f, 0.f, 0.f, 0.f);
    float4* arow = (float4*)(aout + (((size_t)b * SQ + s) << 10));
#pragma unroll
    for (int i = 0; i < 4; i++) {
        int col0 = (h << 9) + (i << 7);
        if (col0 > s + 31 || col0 + 127 < s - 32)
            arow[(col0 >> 2) + ln] = z4;
    }

    // ---- top: one LDG wave -- w tiles + xts halo + was ----
    {
        float* wts = pool + OFF_U1;          // [u][c], stride 68
        float* wxs = wts + UN * 68;
        int u = tid >> 4, g = tid & 15;      // 512 = 32u x 16 groups
        *(float4*)&wts[u * 68 + g * 4] = ((const float4*)Wt)[tid];
        *(float4*)&wxs[u * 68 + g * 4] = ((const float4*)Wx)[tid];
        if (tid < UN) was[tid] = wa[tid];

        int cc = tid >> 3, gq = tid & 7;
        int gb = cc >> 2, clo = cc & 3;
        const float* xb = x + (size_t)b * CH * SQ + cc * SQ;
        if (sblk >= 4 && sblk <= 123) {
            const float4* xb4 = (const float4*)(xb + tlo);   // tlo % 4 == 0
#pragma unroll
            for (int f = 0; f < 3; f++) {
                int fi = gq + f * 8;
                if (fi < 18) {
                    float4 v = xb4[fi];
                    int t0 = fi << 2;
                    xts[(t0 + 0) * 68 + (((((t0 + 0) & 7) ^ gb) << 2) | clo)] = v.x;
                    xts[(t0 + 1) * 68 + (((((t0 + 1) & 7) ^ gb) << 2) | clo)] = v.y;
                    xts[(t0 + 2) * 68 + (((((t0 + 2) & 7) ^ gb) << 2) | clo)] = v.z;
                    xts[(t0 + 3) * 68 + (((((t0 + 3) & 7) ^ gb) << 2) | clo)] = v.w;
                }
            }
        } else {
#pragma unroll
            for (int p = 0; p < 9; p++) {
                int ti = p * 8 + gq;
                int tc = min(max(tlo + ti, 0), SQ - 1);
                int csw = ((gb ^ gq) << 2) | clo;   // ti&7 == gq
                xts[ti * 68 + csw] = xb[tc];
            }
        }
    }
    __syncthreads();                         // SYNC_A

    // ---- phase 1: q (warps 0-7) / k (warps 8-15), x rows from xts ----
    {
        const float* wts = pool + OFF_U1;
        const float* wxs = wts + UN * 68;
        int ss = wid & 7;                    // own row index
        const float* wrow = (tid < 256) ? &wts[ln * 68] : &wxs[ln * 68];
        const float4* xp = (const float4*)&xts[(32 + ss) * 68];
        float a0 = 0.f, a1 = 0.f, a2 = 0.f, a3 = 0.f;
#pragma unroll
        for (int gg = 0; gg < 16; gg++) {    // gg = stored (swizzled) group
            float4 x4 = xp[gg];
            int wg = (gg & 8) | ((gg & 7) ^ ss);   // original channel group
            float4 w4 = *(const float4*)&wrow[wg * 4];
            a0 = fmaf(x4.x, w4.x, a0); a1 = fmaf(x4.y, w4.y, a1);
            a2 = fmaf(x4.z, w4.z, a2); a3 = fmaf(x4.w, w4.w, a3);
        }
        float res = (a0 + a1) + (a2 + a3);
        if (tid < 256) {
            qs[ss * 32 + ln] = res;
        } else {
            g_k[((size_t)b * SQ + s0 + ss) * UN + ln] = res + bh[ln];  // bh folded
        }
    }
    __syncthreads();                         // SYNC_B: k stored, wts free

    // ---- release + per-warp neighbor spin + ks fill (warps 0..8) ----
    float* ks = pool + OFF_U1;               // [ti][u], stride 36 (odd 16B units)
    if (wid <= 8) {
        if (ln == 0) {
            __threadfence();                 // release own k stores
            unsigned v = atomicAdd(&g_flag[blockIdx.x], 1u);
            unsigned base = v - (v % 9u);    // 9*(launchN-1)
            int owner = min(max(sblk - 4 + wid, 0), 127);
            volatile unsigned* f = (volatile unsigned*)&g_flag[(b << 7) + owner];
            while (*f <= base) { }
            __threadfence();                 // acquire
        }
        __syncwarp();
        const float4* gk4 = (const float4*)g_k;
#pragma unroll
        for (int rep = 0; rep < 2; rep++) {
            int lin = ln + (rep << 5);       // 0..63
            int ti = (wid << 3) + (lin >> 3);
            int gq = lin & 7;
            int tc = min(max(tlo + ti, 0), SQ - 1);
            *(float4*)&ks[ti * 36 + gq * 4] = gk4[((size_t)b * SQ + tc) * 8 + gq];
        }
    }
    __syncthreads();                         // SYNC_D: ks ready

    // ---- scores + softmax (no max-shift; bounded scores, eps-only error) ----
    int j = h * 32 + ln;
    int t = s - 32 + j;
    bool valid = (t >= 0) && (t < SQ);
    int ti = r + j;                          // <= 70

    const float4* kp = (const float4*)&ks[ti * 36];
    const float4* qp = (const float4*)&qs[r * 32];
    const float4* wap = (const float4*)was;
    float acc = 0.f;
#pragma unroll
    for (int g = 0; g < 8; g++) {
        float4 q4 = qp[g];
        float4 w4 = wap[g];
        float4 k4 = kp[g];
        acc = fmaf(w4.x, htanh(q4.x + k4.x), acc);
        acc = fmaf(w4.y, htanh(q4.y + k4.y), acc);
        acc = fmaf(w4.z, htanh(q4.z + k4.z), acc);
        acc = fmaf(w4.w, htanh(q4.w + k4.w), acc);
    }

    float* a_s = pool + OFF_AS;
    float e = valid ? __expf(acc) : 0.f;
    float sm = e;
#pragma unroll
    for (int o = 16; o > 0; o >>= 1) sm += __shfl_xor_sync(0xffffffffu, sm, o);
    if (ln == 0) sumb[r * 2 + h] = sm;
    a_s[(r << 6) + j] = e;                   // unnormalized
    __syncthreads();                         // SYNC_E

    float inv = __fdividef(1.f, sumb[r * 2] + sumb[r * 2 + 1] + 1e-7f);

    // ---- a row write: ACTIVE segments only ----
#pragma unroll
    for (int i = 0; i < 4; i++) {
        int col0 = (h << 9) + (i << 7);
        if (!(col0 > s + 31 || col0 + 127 < s - 32)) {
            int col = col0 + (ln << 2);
            int jw = col - s + 32;
            float4 val;
            val.x = ((unsigned)(jw + 0) < 64u) ? a_s[(r << 6) + jw + 0] * inv : 0.f;
            val.y = ((unsigned)(jw + 1) < 64u) ? a_s[(r << 6) + jw + 1] * inv : 0.f;
            val.z = ((unsigned)(jw + 2) < 64u) ? a_s[(r << 6) + jw + 2] * inv : 0.f;
            val.w = ((unsigned)(jw + 3) < 64u) ? a_s[(r << 6) + jw + 3] * inv : 0.f;
            arow[col >> 2] = val;
        }
    }

    // ---- v pass: 16 c-groups x 4 j-segments per row; staggered vs rows ----
    float* vs = pool + OFF_U1 + 2592;        // staggered: f(pseg)=pseg*68+r*4
    {
        int q64 = tid & 63;
        int cgrp = q64 & 15;
        int jseg = q64 >> 4;
        float4 vacc = z4;
#pragma unroll
        for (int it2 = 0; it2 < 4; it2++) {
            float4 a4 = *(const float4*)&a_s[(r << 6) + (jseg << 4) + (it2 << 2)];
            int jb = (jseg << 4) + (it2 << 2);
#pragma unroll
            for (int ee = 0; ee < 4; ee++) {
                int row = r + jb + ee;
                float av = (ee == 0) ? a4.x : (ee == 1) ? a4.y : (ee == 2) ? a4.z : a4.w;
                float4 x4 = *(const float4*)&xts[row * 68 + ((cgrp ^ (row & 7)) << 2)];
                vacc.x = fmaf(av, x4.x, vacc.x);
                vacc.y = fmaf(av, x4.y, vacc.y);
                vacc.z = fmaf(av, x4.z, vacc.z);
                vacc.w = fmaf(av, x4.w, vacc.w);
            }
        }
        vacc.x *= inv; vacc.y *= inv; vacc.z *= inv; vacc.w *= inv;
        int pseg = (r << 2) + jseg;
        *(float4*)&vs[pseg * 68 + (r << 2) + (cgrp << 2)] = vacc;
    }
    __syncthreads();                         // SYNC_F

    // ---- combine 4 j-segment partials (conflict-free banks) + v write ----
    {
        int c = tid >> 3, i = tid & 7;
        int base = (i * 4) * 68 + i * 4 + c;       // f(i*4+p)+c = (i*4+p)*68+i*4+c
        float vsum = (vs[base] + vs[base + 68]) +
                     (vs[base + 136] + vs[base + 204]);
        vout[(size_t)b * CH * SQ + c * SQ + s0 + i] = vsum;
    }
}

extern "C" void kernel_launch(void* const* d_in, const int* in_sizes, int n_in,
                              void* d_out, int out_size) {
    (void)in_sizes; (void)n_in; (void)out_size;
    const float* x  = (const float*)d_in[0];
    const float* Wt = (const float*)d_in[1];
    const float* Wx = (const float*)d_in[2];
    const float* Wa = (const float*)d_in[3];
    // d_in[4] = Wa_b: cancels exactly in the softmax, unused
    const float* bh = (const float*)d_in[5];

    float* vout = (float*)d_out;                     // (B, C, S)
    float* aout = vout + (size_t)BS * CH * SQ;       // (B, S, S)

    fused_kernel<<<GRID, 512>>>(x, Wt, Wx, bh, Wa, vout, aout);
}